// round 8
// baseline (speedup 1.0000x reference)
#include <cuda_runtime.h>
#include <cuda_bf16.h>
#include <cstdint>
#include <cstddef>

// ---------------------------------------------------------------------------
// Problem constants
// ---------------------------------------------------------------------------
#define HN   1024
#define SN   8192
#define TN   48
#define START_TAG 46
#define END_TAG   47
#define NEGV (-10000.0f)
#define POISON 0x7fc0deadu   // NaN payload; o*tanh(c) can never produce it
#define NREP 8               // h-mailbox replicas (anti-contention)

// ---------------------------------------------------------------------------
// Scratch (device globals; no runtime allocation allowed)
// ---------------------------------------------------------------------------
__device__ float g_XI[2][SN][4 * HN];       // x@W_ih^T + biases (dir 1 in step order)
__device__ float g_Hseq[2][SN][HN];         // h sequences, dir 1 reversed to sentence order
__device__ float g_Hbuf[2][4][NREP][HN];    // [dir][slot][replica][j] self-signaling h exchange
__device__ float g_feats[SN * TN];
__device__ unsigned char g_bp[SN * TN];

__device__ __forceinline__ uint4 ldacq4(const uint4* p) {
    uint4 v;
    asm volatile("ld.global.acquire.gpu.v4.u32 {%0,%1,%2,%3}, [%4];"
                 : "=r"(v.x), "=r"(v.y), "=r"(v.z), "=r"(v.w) : "l"(p));
    return v;
}
__device__ __forceinline__ void strel_f(float* p, float v) {
    asm volatile("st.global.release.gpu.b32 [%0], %1;"
                 :: "l"(p), "r"(__float_as_uint(v)) : "memory");
}

// ---------------------------------------------------------------------------
// Init: slot 0 = zeros (h0 = 0) in all replicas, slots 1..3 = poison.
// Must run every launch (graph replays).
// ---------------------------------------------------------------------------
__global__ void init_kernel() {
    int tid = blockIdx.x * blockDim.x + threadIdx.x;
    unsigned* hb = (unsigned*)&g_Hbuf[0][0][0][0];
    const int total = 2 * 4 * NREP * HN;
    for (int i = tid; i < total; i += gridDim.x * blockDim.x) {
        int slot = (i / (NREP * HN)) & 3;
        hb[i] = (slot == 0) ? 0u : POISON;
    }
}

// ---------------------------------------------------------------------------
// Kernel A: XI = x @ W_ih^T + (b_ih + b_hh)  for both directions.
// Tiled SGEMM: BM=BN=128, BK=16, 256 threads, 8x8 microtile. (known-good)
// ---------------------------------------------------------------------------
#define BM 128
#define BN 128
#define BK 16

__global__ void __launch_bounds__(256) xi_gemm_kernel(
    const float* __restrict__ x,
    const float* __restrict__ Wf, const float* __restrict__ Wb,
    const float* __restrict__ bihf, const float* __restrict__ bhhf,
    const float* __restrict__ bihb, const float* __restrict__ bhhb)
{
    __shared__ float As[BK][BM + 4];
    __shared__ float Bs[BK][BN + 4];

    const int z  = blockIdx.z;
    const float* W  = z ? Wb   : Wf;
    const float* b1 = z ? bihb : bihf;
    const float* b2 = z ? bhhb : bhhf;

    const int m0 = blockIdx.y * BM;
    const int n0 = blockIdx.x * BN;
    const int tid = threadIdx.x;

    const int lr = tid >> 2;          // 0..63
    const int lc = (tid & 3) << 2;    // 0,4,8,12
    const int ty = tid >> 4;          // 0..15
    const int tx = tid & 15;          // 0..15

    float acc[8][8];
#pragma unroll
    for (int i = 0; i < 8; i++)
#pragma unroll
        for (int j = 0; j < 8; j++) acc[i][j] = 0.0f;

    for (int k0 = 0; k0 < HN; k0 += BK) {
        float4 va0 = *(const float4*)&x[(size_t)(m0 + lr)       * HN + k0 + lc];
        float4 va1 = *(const float4*)&x[(size_t)(m0 + lr + 64)  * HN + k0 + lc];
        float4 vb0 = *(const float4*)&W[(size_t)(n0 + lr)       * HN + k0 + lc];
        float4 vb1 = *(const float4*)&W[(size_t)(n0 + lr + 64)  * HN + k0 + lc];

        As[lc + 0][lr] = va0.x; As[lc + 1][lr] = va0.y; As[lc + 2][lr] = va0.z; As[lc + 3][lr] = va0.w;
        As[lc + 0][lr + 64] = va1.x; As[lc + 1][lr + 64] = va1.y; As[lc + 2][lr + 64] = va1.z; As[lc + 3][lr + 64] = va1.w;
        Bs[lc + 0][lr] = vb0.x; Bs[lc + 1][lr] = vb0.y; Bs[lc + 2][lr] = vb0.z; Bs[lc + 3][lr] = vb0.w;
        Bs[lc + 0][lr + 64] = vb1.x; Bs[lc + 1][lr + 64] = vb1.y; Bs[lc + 2][lr + 64] = vb1.z; Bs[lc + 3][lr + 64] = vb1.w;
        __syncthreads();

#pragma unroll
        for (int kk = 0; kk < BK; kk++) {
            float a[8], b[8];
            *(float4*)&a[0] = *(const float4*)&As[kk][ty * 8];
            *(float4*)&a[4] = *(const float4*)&As[kk][ty * 8 + 4];
            *(float4*)&b[0] = *(const float4*)&Bs[kk][tx * 8];
            *(float4*)&b[4] = *(const float4*)&Bs[kk][tx * 8 + 4];
#pragma unroll
            for (int i = 0; i < 8; i++)
#pragma unroll
                for (int j = 0; j < 8; j++) acc[i][j] += a[i] * b[j];
        }
        __syncthreads();
    }

    float bias[8];
#pragma unroll
    for (int j = 0; j < 8; j++) {
        int n = n0 + tx * 8 + j;
        bias[j] = b1[n] + b2[n];
    }
#pragma unroll
    for (int i = 0; i < 8; i++) {
        int m = m0 + ty * 8 + i;
        int row = z ? (SN - 1 - m) : m;
        float* outr = &g_XI[z][row][n0 + tx * 8];
        float4 v0, v1;
        v0.x = acc[i][0] + bias[0]; v0.y = acc[i][1] + bias[1];
        v0.z = acc[i][2] + bias[2]; v0.w = acc[i][3] + bias[3];
        v1.x = acc[i][4] + bias[4]; v1.y = acc[i][5] + bias[5];
        v1.z = acc[i][6] + bias[6]; v1.w = acc[i][7] + bias[7];
        *(float4*)outr = v0;
        *(float4*)(outr + 4) = v1;
    }
}

// ---------------------------------------------------------------------------
// Kernel B: persistent BiLSTM recurrence.
// 128 blocks x 256 threads. Block b: dir = b>>6, outputs [jbase, jbase+16).
// Warp w owns ALL 4 gate rows for outputs {jbase+2w, jbase+2w+1}:
//   regs  = 4 rows (e=0: output 2w,  gates 0..3)
//   smem  = 4 rows (e=1: output 2w+1, gates 0..3)
// After the butterfly reduction lanes 0/1 do the gate math + publish directly
// (no gsum smem round-trip, one __syncthreads per step, double-buffered hs).
//
// h exchange: 8 replicated mailboxes, 4 parities, poison-signaled.
// Consumer block polls ONLY its replica rep=(b&63)>>3 (cuts L2 hot-line
// contention 8x). Publishers store h to all 8 replicas with release; the same
// threads poisoned this block's 128-float share of slot (t+2)&3 earlier in
// the step, so the release orders the poison (R7 invariant preserved).
// ---------------------------------------------------------------------------
#define NBLK 128
#define OPB  16
#define LSTM_SMEM ((32 * 1024 + 2 * 1024) * 4)

__device__ __forceinline__ float sigf(float x) { return 1.0f / (1.0f + __expf(-x)); }

__global__ void __launch_bounds__(256, 1) lstm_kernel(
    const float* __restrict__ Whh_f, const float* __restrict__ Whh_b)
{
    extern __shared__ float sm[];
    float* wsh = sm;                     // 32 rows * 1024 (smem-resident weight rows)
    float* hs  = sm + 32 * 1024;         // 2 x 1024 (h_prev, double-buffered)

    const int tid  = threadIdx.x;
    const int w    = tid >> 5;
    const int lane = tid & 31;
    const int b    = blockIdx.x;
    const int dir  = b >> 6;
    const int blk  = b & 63;
    const int jbase = blk * OPB;
    const int rep  = blk >> 3;           // this block's mailbox replica
    const int sub  = blk & 7;            // poison share within the replica
    const float* Whh = dir ? Whh_b : Whh_f;

    // weights: e=0 rows (output 2w, gates 0..3) -> regs; e=1 rows -> smem
    float4 wr[4][8];
#pragma unroll
    for (int q = 0; q < 4; q++) {
        const float4* src = (const float4*)(Whh + (size_t)(q * HN + jbase + 2 * w) * HN);
#pragma unroll
        for (int m = 0; m < 8; m++) wr[q][m] = src[lane + 32 * m];
    }
#pragma unroll
    for (int q = 0; q < 4; q++) {
        const float4* src = (const float4*)(Whh + (size_t)(q * HN + jbase + 2 * w + 1) * HN);
        float4* dst = (float4*)(wsh + (size_t)(w * 4 + q) * HN);
#pragma unroll
        for (int m = 0; m < 8; m++) dst[lane + 32 * m] = src[lane + 32 * m];
    }

    const int jout = jbase + 2 * w + lane;   // valid for lane < 2
    float c_state = 0.0f;

    for (int t = 0; t < SN; t++) {
        // prefetch xi for this step (lanes 0,1 of each warp; hidden by poll)
        float xi0 = 0.f, xi1 = 0.f, xi2 = 0.f, xi3 = 0.f;
        if (lane < 2) {
            const float* xr = &g_XI[dir][t][0];
            xi0 = __ldg(xr + 0 * HN + jout);
            xi1 = __ldg(xr + 1 * HN + jout);
            xi2 = __ldg(xr + 2 * HN + jout);
            xi3 = __ldg(xr + 3 * HN + jout);
        }

        // consume h_t from OUR replica: poll own 16B quad until valid,
        // stage straight into smem (double-buffered).
        float* hcur = hs + (t & 1) * HN;
        {
            const uint4* src = (const uint4*)&g_Hbuf[dir][t & 3][rep][0] + tid;
            uint4 v;
            do {
                v = ldacq4(src);
            } while (v.x == POISON || v.y == POISON || v.z == POISON || v.w == POISON);
            ((uint4*)hcur)[tid] = v;
        }
        __syncthreads();

        // poison our 128-float share of slot (t+2)&3 in OUR replica.
        // Done by the publisher threads (lane<2) so the release publish below
        // orders these stores (same thread, program order).
        if (lane < 2) {
            float* pz = &g_Hbuf[dir][(t + 2) & 3][rep][sub * 128 + (w * 2 + lane) * 8];
            uint4 p4 = make_uint4(POISON, POISON, POISON, POISON);
            *(uint4*)pz = p4;
            *(uint4*)(pz + 4) = p4;
        }

        // h chunk into registers
        float4 hv[8];
#pragma unroll
        for (int m = 0; m < 8; m++) hv[m] = ((const float4*)hcur)[lane + 32 * m];

        float acc[8];
#pragma unroll
        for (int r = 0; r < 8; r++) acc[r] = 0.0f;

        // register rows (e=0): acc[0..3] = gates 0..3 of output 2w
#pragma unroll
        for (int q = 0; q < 4; q++) {
#pragma unroll
            for (int m = 0; m < 8; m++) {
                float4 ww = wr[q][m];
                acc[q] += ww.x * hv[m].x + ww.y * hv[m].y + ww.z * hv[m].z + ww.w * hv[m].w;
            }
        }
        // smem rows (e=1): acc[4..7] = gates 0..3 of output 2w+1
#pragma unroll
        for (int q = 0; q < 4; q++) {
            const float4* wp = (const float4*)(wsh + (size_t)(w * 4 + q) * HN);
            float a = 0.0f;
#pragma unroll
            for (int m = 0; m < 8; m++) {
                float4 ww = wp[lane + 32 * m];
                a += ww.x * hv[m].x + ww.y * hv[m].y + ww.z * hv[m].z + ww.w * hv[m].w;
            }
            acc[4 + q] = a;
        }

        // butterfly reduce: every lane ends with all 8 totals
#pragma unroll
        for (int r = 0; r < 8; r++) {
#pragma unroll
            for (int o = 16; o > 0; o >>= 1)
                acc[r] += __shfl_xor_sync(0xffffffffu, acc[r], o);
        }

        // gates + publish (lane 0: output 2w via acc[0..3]; lane 1: 2w+1 via acc[4..7])
        if (lane < 2) {
            const int base = lane * 4;
            float gi = acc[base + 0] + xi0;
            float gf = acc[base + 1] + xi1;
            float gg = acc[base + 2] + xi2;
            float go = acc[base + 3] + xi3;
            float si = sigf(gi);
            float sf = sigf(gf);
            float tg = tanhf(gg);
            float so = sigf(go);
            c_state = sf * c_state + si * tg;
            float hout = so * tanhf(c_state);

            float* dst = &g_Hbuf[dir][(t + 1) & 3][0][jout];
#pragma unroll
            for (int r = 0; r < NREP; r++) strel_f(dst + r * HN, hout);

            int srow = dir ? (SN - 1 - t) : t;
            g_Hseq[dir][srow][jout] = hout;
        }
    }
}

// ---------------------------------------------------------------------------
// Kernel C: feats = concat(hf, hb) @ W_dense^T + b_dense. 4 rows per block.
// ---------------------------------------------------------------------------
__global__ void __launch_bounds__(256) dense_kernel(
    const float* __restrict__ Wd, const float* __restrict__ bd)
{
    __shared__ float hsm[4][2 * HN];
    const int tid  = threadIdx.x;
    const int w    = tid >> 5;
    const int lane = tid & 31;
    const int s0   = blockIdx.x * 4;

    for (int i = tid; i < 4 * 512; i += 256) {
        int r = i >> 9, f4 = i & 511;
        float4 v;
        if (f4 < 256) v = *(const float4*)&g_Hseq[0][s0 + r][f4 * 4];
        else          v = *(const float4*)&g_Hseq[1][s0 + r][(f4 - 256) * 4];
        *(float4*)&hsm[r][f4 * 4] = v;
    }
    __syncthreads();

    for (int idx = w; idx < 4 * TN; idx += 8) {
        int r = idx / TN, tag = idx - r * TN;
        const float4* wrow = (const float4*)(Wd + (size_t)tag * 2 * HN);
        const float4* hrow = (const float4*)&hsm[r][0];
        float acc = 0.0f;
#pragma unroll
        for (int m = 0; m < 16; m++) {
            float4 a  = wrow[lane + 32 * m];
            float4 h4 = hrow[lane + 32 * m];
            acc += a.x * h4.x + a.y * h4.y + a.z * h4.z + a.w * h4.w;
        }
#pragma unroll
        for (int o = 16; o > 0; o >>= 1) acc += __shfl_xor_sync(0xffffffffu, acc, o);
        if (lane == 0) g_feats[(s0 + r) * TN + tag] = acc + __ldg(&bd[tag]);
    }
}

// ---------------------------------------------------------------------------
// Kernel D: Viterbi forward + chunked smem backtrack (validated).
// 2 threads per tag row, 4 compare chains each; first-max tie-break preserved.
// ---------------------------------------------------------------------------
__global__ void __launch_bounds__(128) viterbi_kernel(
    const float* __restrict__ trans, float* __restrict__ out, int out_size)
{
    __shared__ float fvb[2][TN];
    __shared__ unsigned char bpc[256 * TN];   // 12 KB backtrack chunk
    const int tid  = threadIdx.x;
    const int row  = tid >> 1;
    const int half = tid & 1;

    float tr[24];
    if (tid < 96) {
#pragma unroll
        for (int j = 0; j < 24; j++) tr[j] = __ldg(&trans[row * TN + half * 24 + j]);
    }
    if (tid < TN) fvb[0][tid] = (tid == START_TAG) ? 0.0f : NEGV;
    __syncthreads();

    for (int s = 0; s < SN; s++) {
        const float* fv = fvb[s & 1];
        float* fvn = fvb[(s + 1) & 1];
        if (tid < 96) {
            float feat = half ? 0.0f : __ldg(&g_feats[s * TN + row]);
            const int jb = half * 24;
            float b0 = fv[jb + 0]  + tr[0];  int a0 = jb + 0;
            float b1 = fv[jb + 6]  + tr[6];  int a1 = jb + 6;
            float b2 = fv[jb + 12] + tr[12]; int a2 = jb + 12;
            float b3 = fv[jb + 18] + tr[18]; int a3 = jb + 18;
#pragma unroll
            for (int k = 1; k < 6; k++) {
                float v0 = fv[jb + k]      + tr[k];      if (v0 > b0) { b0 = v0; a0 = jb + k; }
                float v1 = fv[jb + 6 + k]  + tr[6 + k];  if (v1 > b1) { b1 = v1; a1 = jb + 6 + k; }
                float v2 = fv[jb + 12 + k] + tr[12 + k]; if (v2 > b2) { b2 = v2; a2 = jb + 12 + k; }
                float v3 = fv[jb + 18 + k] + tr[18 + k]; if (v3 > b3) { b3 = v3; a3 = jb + 18 + k; }
            }
            if (b1 > b0) { b0 = b1; a0 = a1; }
            if (b3 > b2) { b2 = b3; a2 = a3; }
            if (b2 > b0) { b0 = b2; a0 = a2; }
            float bo = __shfl_xor_sync(0xffffffffu, b0, 1);
            int   ao = __shfl_xor_sync(0xffffffffu, a0, 1);
            if (half == 0) {
                if (bo > b0) { b0 = bo; a0 = ao; }  // other half's indices all larger
                fvn[row] = b0 + feat;
                g_bp[s * TN + row] = (unsigned char)a0;
            }
        }
        __syncthreads();
    }

    __shared__ int s_arg;
    if (tid == 0) {
        float best = -3.4e38f; int arg = 0;
        const float* fvf = fvb[SN & 1];
        for (int i = 0; i < TN; i++) {
            float v = fvf[i] + __ldg(&trans[END_TAG * TN + i]);
            if (v > best) { best = v; arg = i; }
        }
        if (out_size > 0) out[0] = best;
        if (SN < out_size) out[SN] = (float)arg;
        s_arg = arg;
    }
    __syncthreads();

    int cur = s_arg;  // live in tid 0 only
    for (int c0 = SN - 256; c0 >= 0; c0 -= 256) {
        const uint4* src = (const uint4*)&g_bp[c0 * TN];
        uint4* dst = (uint4*)bpc;
        for (int i = tid; i < 256 * TN / 16; i += 128) dst[i] = src[i];
        __syncthreads();
        if (tid == 0) {
            int hi = c0 + 255; if (hi > SN - 1) hi = SN - 1;
            int lo = (c0 > 0) ? c0 : 1;
            for (int s = hi; s >= lo; s--) {
                cur = bpc[(s - c0) * TN + cur];
                if (s < out_size) out[s] = (float)cur;
            }
        }
        __syncthreads();
    }
}

// ---------------------------------------------------------------------------
// Launch
// ---------------------------------------------------------------------------
extern "C" void kernel_launch(void* const* d_in, const int* in_sizes, int n_in,
                              void* d_out, int out_size)
{
    const float* sentence    = (const float*)d_in[0];
    const float* W_ih_f      = (const float*)d_in[1];
    const float* W_hh_f      = (const float*)d_in[2];
    const float* b_ih_f      = (const float*)d_in[3];
    const float* b_hh_f      = (const float*)d_in[4];
    const float* W_ih_b      = (const float*)d_in[5];
    const float* W_hh_b      = (const float*)d_in[6];
    const float* b_ih_b      = (const float*)d_in[7];
    const float* b_hh_b      = (const float*)d_in[8];
    const float* W_dense     = (const float*)d_in[9];
    const float* b_dense     = (const float*)d_in[10];
    const float* transitions = (const float*)d_in[11];
    float* out = (float*)d_out;

    (void)in_sizes; (void)n_in;

    cudaFuncSetAttribute(lstm_kernel, cudaFuncAttributeMaxDynamicSharedMemorySize, LSTM_SMEM);

    init_kernel<<<64, 256>>>();

    dim3 ggemm(4 * HN / BN, SN / BM, 2);
    xi_gemm_kernel<<<ggemm, 256>>>(sentence, W_ih_f, W_ih_b,
                                   b_ih_f, b_hh_f, b_ih_b, b_hh_b);

    lstm_kernel<<<NBLK, 256, LSTM_SMEM>>>(W_hh_f, W_hh_b);

    dense_kernel<<<SN / 4, 256>>>(W_dense, b_dense);

    viterbi_kernel<<<1, 128>>>(transitions, out, out_size);
}

// round 9
// speedup vs baseline: 1.9153x; 1.9153x over previous
#include <cuda_runtime.h>
#include <cuda_bf16.h>
#include <cstdint>
#include <cstddef>

// ---------------------------------------------------------------------------
// Problem constants
// ---------------------------------------------------------------------------
#define HN   1024
#define SN   8192
#define TN   48
#define START_TAG 46
#define END_TAG   47
#define NEGV (-10000.0f)
#define POISON 0x7fc0deadu   // NaN payload; o*tanh(c) can never produce it
#define NREP 8               // h-mailbox replicas (anti-contention)

// ---------------------------------------------------------------------------
// Scratch (device globals; no runtime allocation allowed)
// ---------------------------------------------------------------------------
__device__ float g_XI[2][SN][4 * HN];       // x@W_ih^T + biases (dir 1 in step order)
__device__ float g_Hseq[2][SN][HN];         // h sequences, dir 1 reversed to sentence order
__device__ float g_Hbuf[2][4][NREP][HN];    // [dir][slot][replica][j] self-signaling h exchange
__device__ float g_feats[SN * TN];
__device__ unsigned char g_bp[SN * TN];

__device__ __forceinline__ uint4 ldacq4(const uint4* p) {
    uint4 v;
    asm volatile("ld.global.acquire.gpu.v4.u32 {%0,%1,%2,%3}, [%4];"
                 : "=r"(v.x), "=r"(v.y), "=r"(v.z), "=r"(v.w) : "l"(p));
    return v;
}
__device__ __forceinline__ void strelax_f(float* p, float v) {
    asm volatile("st.global.relaxed.gpu.b32 [%0], %1;"
                 :: "l"(p), "r"(__float_as_uint(v)) : "memory");
}
__device__ __forceinline__ void fence_gpu() {
    asm volatile("fence.acq_rel.gpu;" ::: "memory");
}

// ---------------------------------------------------------------------------
// Init: slot 0 = zeros (h0 = 0) in all replicas, slots 1..3 = poison.
// Must run every launch (graph replays).
// ---------------------------------------------------------------------------
__global__ void init_kernel() {
    int tid = blockIdx.x * blockDim.x + threadIdx.x;
    unsigned* hb = (unsigned*)&g_Hbuf[0][0][0][0];
    const int total = 2 * 4 * NREP * HN;
    for (int i = tid; i < total; i += gridDim.x * blockDim.x) {
        int slot = (i / (NREP * HN)) & 3;
        hb[i] = (slot == 0) ? 0u : POISON;
    }
}

// ---------------------------------------------------------------------------
// Kernel A: XI = x @ W_ih^T + (b_ih + b_hh)  for both directions.
// Tiled SGEMM: BM=BN=128, BK=16, 256 threads, 8x8 microtile. (known-good)
// ---------------------------------------------------------------------------
#define BM 128
#define BN 128
#define BK 16

__global__ void __launch_bounds__(256) xi_gemm_kernel(
    const float* __restrict__ x,
    const float* __restrict__ Wf, const float* __restrict__ Wb,
    const float* __restrict__ bihf, const float* __restrict__ bhhf,
    const float* __restrict__ bihb, const float* __restrict__ bhhb)
{
    __shared__ float As[BK][BM + 4];
    __shared__ float Bs[BK][BN + 4];

    const int z  = blockIdx.z;
    const float* W  = z ? Wb   : Wf;
    const float* b1 = z ? bihb : bihf;
    const float* b2 = z ? bhhb : bhhf;

    const int m0 = blockIdx.y * BM;
    const int n0 = blockIdx.x * BN;
    const int tid = threadIdx.x;

    const int lr = tid >> 2;          // 0..63
    const int lc = (tid & 3) << 2;    // 0,4,8,12
    const int ty = tid >> 4;          // 0..15
    const int tx = tid & 15;          // 0..15

    float acc[8][8];
#pragma unroll
    for (int i = 0; i < 8; i++)
#pragma unroll
        for (int j = 0; j < 8; j++) acc[i][j] = 0.0f;

    for (int k0 = 0; k0 < HN; k0 += BK) {
        float4 va0 = *(const float4*)&x[(size_t)(m0 + lr)       * HN + k0 + lc];
        float4 va1 = *(const float4*)&x[(size_t)(m0 + lr + 64)  * HN + k0 + lc];
        float4 vb0 = *(const float4*)&W[(size_t)(n0 + lr)       * HN + k0 + lc];
        float4 vb1 = *(const float4*)&W[(size_t)(n0 + lr + 64)  * HN + k0 + lc];

        As[lc + 0][lr] = va0.x; As[lc + 1][lr] = va0.y; As[lc + 2][lr] = va0.z; As[lc + 3][lr] = va0.w;
        As[lc + 0][lr + 64] = va1.x; As[lc + 1][lr + 64] = va1.y; As[lc + 2][lr + 64] = va1.z; As[lc + 3][lr + 64] = va1.w;
        Bs[lc + 0][lr] = vb0.x; Bs[lc + 1][lr] = vb0.y; Bs[lc + 2][lr] = vb0.z; Bs[lc + 3][lr] = vb0.w;
        Bs[lc + 0][lr + 64] = vb1.x; Bs[lc + 1][lr + 64] = vb1.y; Bs[lc + 2][lr + 64] = vb1.z; Bs[lc + 3][lr + 64] = vb1.w;
        __syncthreads();

#pragma unroll
        for (int kk = 0; kk < BK; kk++) {
            float a[8], b[8];
            *(float4*)&a[0] = *(const float4*)&As[kk][ty * 8];
            *(float4*)&a[4] = *(const float4*)&As[kk][ty * 8 + 4];
            *(float4*)&b[0] = *(const float4*)&Bs[kk][tx * 8];
            *(float4*)&b[4] = *(const float4*)&Bs[kk][tx * 8 + 4];
#pragma unroll
            for (int i = 0; i < 8; i++)
#pragma unroll
                for (int j = 0; j < 8; j++) acc[i][j] += a[i] * b[j];
        }
        __syncthreads();
    }

    float bias[8];
#pragma unroll
    for (int j = 0; j < 8; j++) {
        int n = n0 + tx * 8 + j;
        bias[j] = b1[n] + b2[n];
    }
#pragma unroll
    for (int i = 0; i < 8; i++) {
        int m = m0 + ty * 8 + i;
        int row = z ? (SN - 1 - m) : m;
        float* outr = &g_XI[z][row][n0 + tx * 8];
        float4 v0, v1;
        v0.x = acc[i][0] + bias[0]; v0.y = acc[i][1] + bias[1];
        v0.z = acc[i][2] + bias[2]; v0.w = acc[i][3] + bias[3];
        v1.x = acc[i][4] + bias[4]; v1.y = acc[i][5] + bias[5];
        v1.z = acc[i][6] + bias[6]; v1.w = acc[i][7] + bias[7];
        *(float4*)outr = v0;
        *(float4*)(outr + 4) = v1;
    }
}

// ---------------------------------------------------------------------------
// Kernel B: persistent BiLSTM recurrence (R7 compute core, replicated mailbox).
// 128 blocks x 256 threads. Block b: dir = b>>6, h-outputs [jbase, jbase+16).
// 64 gate rows/block; warp w owns rows [8w, 8w+8): 4 rows register-resident,
// 4 rows SMEM-resident (128 weight regs/thread -> no spill).
//
// h exchange: 8 replicated mailboxes, 4 parities, poison-signaled.
//  - consumer polls ONLY its replica rep=(b&63)>>3 with acquire v4 loads
//    (8x less L2 hot-line contention than R7's single mailbox).
//  - publisher threads (tid<16): poison their block's 128-float share of
//    slot (t+2)&3 in their replica early in the step, then at publish time
//    issue ONE fence.acq_rel.gpu followed by 8 RELAXED stores (one per
//    replica). fence-release + relaxed store observed by acquire load gives
//    the same synchronizes-with edge as R8's release stores WITHOUT the 8x
//    serialized release round-trips.
//  - safety lattice identical to R7/R8: any block at step t implies all
//    blocks finished step t-1 entirely, so nobody can still be reading slot
//    (t+2)&3 when it is poisoned at step t, and every h-write into a slot
//    happens-after that slot's poison via the fence/acquire chain.
// ---------------------------------------------------------------------------
#define NBLK 128
#define OPB  16
#define LSTM_SMEM ((32 * 1024 + 1024 + 64) * 4)

__device__ __forceinline__ float sigf(float x) { return 1.0f / (1.0f + __expf(-x)); }

__global__ void __launch_bounds__(256, 1) lstm_kernel(
    const float* __restrict__ Whh_f, const float* __restrict__ Whh_b)
{
    extern __shared__ float sm[];
    float* wsh  = sm;                    // 32*1024 floats (smem-resident rows)
    float* hs   = sm + 32 * 1024;        // 1024 floats (h_prev)
    float* gsum = hs + 1024;             // 64 row sums

    const int tid  = threadIdx.x;
    const int w    = tid >> 5;
    const int lane = tid & 31;
    const int b    = blockIdx.x;
    const int dir  = b >> 6;
    const int blk  = b & 63;
    const int jbase = blk * OPB;
    const int rep  = blk >> 3;           // mailbox replica this block polls
    const int sub  = blk & 7;            // poison share within that replica
    const float* Whh = dir ? Whh_b : Whh_f;

    // -------- load weights: rows 8w..8w+3 -> regs, 8w+4..8w+7 -> smem -------
    float4 wr[4][8];
#pragma unroll
    for (int q = 0; q < 4; q++) {
        int rr = 8 * w + q;
        int grow = (rr >> 4) * HN + jbase + (rr & 15);
        const float4* src = (const float4*)(Whh + (size_t)grow * HN);
#pragma unroll
        for (int m = 0; m < 8; m++) wr[q][m] = src[lane + 32 * m];
    }
#pragma unroll
    for (int q = 0; q < 4; q++) {
        int rr = 8 * w + 4 + q;
        int grow = (rr >> 4) * HN + jbase + (rr & 15);
        const float4* src = (const float4*)(Whh + (size_t)grow * HN);
        float4* dst = (float4*)(wsh + (size_t)(w * 4 + q) * HN);
#pragma unroll
        for (int m = 0; m < 8; m++) dst[lane + 32 * m] = src[lane + 32 * m];
    }

    float c_state = 0.0f;

    for (int t = 0; t < SN; t++) {
        // prefetch xi for this step (long-latency; hidden behind the poll)
        float xi0 = 0.f, xi1 = 0.f, xi2 = 0.f, xi3 = 0.f;
        if (tid < OPB) {
            const float* xr = &g_XI[dir][t][0];
            xi0 = __ldg(xr + 0 * HN + jbase + tid);
            xi1 = __ldg(xr + 1 * HN + jbase + tid);
            xi2 = __ldg(xr + 2 * HN + jbase + tid);
            xi3 = __ldg(xr + 3 * HN + jbase + tid);
        }

        // consume h_t from OUR replica: every thread polls its own 16B quad
        // until valid, then stages it straight into smem.
        {
            const uint4* src = (const uint4*)&g_Hbuf[dir][t & 3][rep][0] + tid;
            uint4 v;
            do {
                v = ldacq4(src);
            } while (v.x == POISON || v.y == POISON || v.z == POISON || v.w == POISON);
            ((uint4*)hs)[tid] = v;
        }
        __syncthreads();

        // poison our 128-float share of slot (t+2)&3 in OUR replica.
        // Publisher threads do it, so the fence below orders it before the
        // h publish (program order + fence.release semantics).
        if (tid < OPB) {
            float* pz = &g_Hbuf[dir][(t + 2) & 3][rep][sub * 128 + tid * 8];
            uint4 p4 = make_uint4(POISON, POISON, POISON, POISON);
            *(uint4*)pz = p4;
            *(uint4*)(pz + 4) = p4;
        }

        // h chunk into registers
        float4 hv[8];
#pragma unroll
        for (int m = 0; m < 8; m++) hv[m] = ((const float4*)hs)[lane + 32 * m];

        float acc[8];
#pragma unroll
        for (int r = 0; r < 8; r++) acc[r] = 0.0f;

        // register-resident rows
#pragma unroll
        for (int q = 0; q < 4; q++) {
#pragma unroll
            for (int m = 0; m < 8; m++) {
                float4 ww = wr[q][m];
                acc[q] += ww.x * hv[m].x + ww.y * hv[m].y + ww.z * hv[m].z + ww.w * hv[m].w;
            }
        }
        // smem-resident rows
#pragma unroll
        for (int q = 0; q < 4; q++) {
            const float4* wp = (const float4*)(wsh + (size_t)(w * 4 + q) * HN);
            float a = 0.0f;
#pragma unroll
            for (int m = 0; m < 8; m++) {
                float4 ww = wp[lane + 32 * m];
                a += ww.x * hv[m].x + ww.y * hv[m].y + ww.z * hv[m].z + ww.w * hv[m].w;
            }
            acc[4 + q] = a;
        }

        // warp reduction over K
#pragma unroll
        for (int r = 0; r < 8; r++) {
#pragma unroll
            for (int o = 16; o > 0; o >>= 1)
                acc[r] += __shfl_xor_sync(0xffffffffu, acc[r], o);
        }
        if (lane == 0) {
#pragma unroll
            for (int r = 0; r < 8; r++) gsum[8 * w + r] = acc[r];
        }
        __syncthreads();

        // gate assembly + cell update + publish h_{t+1}
        if (tid < OPB) {
            float gi = gsum[tid]          + xi0;
            float gf = gsum[16 + tid]     + xi1;
            float gg = gsum[32 + tid]     + xi2;
            float go = gsum[48 + tid]     + xi3;
            float si = sigf(gi);
            float sf = sigf(gf);
            float tg = tanhf(gg);
            float so = sigf(go);
            c_state = sf * c_state + si * tg;
            float hout = so * tanhf(c_state);
            int j = jbase + tid;

            fence_gpu();   // release: poison (and all prior stores) visible first
            float* dst = &g_Hbuf[dir][(t + 1) & 3][0][j];
#pragma unroll
            for (int r = 0; r < NREP; r++) strelax_f(dst + r * HN, hout);

            int srow = dir ? (SN - 1 - t) : t;
            g_Hseq[dir][srow][j] = hout;
        }
    }
}

// ---------------------------------------------------------------------------
// Kernel C: feats = concat(hf, hb) @ W_dense^T + b_dense. 4 rows per block.
// ---------------------------------------------------------------------------
__global__ void __launch_bounds__(256) dense_kernel(
    const float* __restrict__ Wd, const float* __restrict__ bd)
{
    __shared__ float hsm[4][2 * HN];
    const int tid  = threadIdx.x;
    const int w    = tid >> 5;
    const int lane = tid & 31;
    const int s0   = blockIdx.x * 4;

    for (int i = tid; i < 4 * 512; i += 256) {
        int r = i >> 9, f4 = i & 511;
        float4 v;
        if (f4 < 256) v = *(const float4*)&g_Hseq[0][s0 + r][f4 * 4];
        else          v = *(const float4*)&g_Hseq[1][s0 + r][(f4 - 256) * 4];
        *(float4*)&hsm[r][f4 * 4] = v;
    }
    __syncthreads();

    for (int idx = w; idx < 4 * TN; idx += 8) {
        int r = idx / TN, tag = idx - r * TN;
        const float4* wrow = (const float4*)(Wd + (size_t)tag * 2 * HN);
        const float4* hrow = (const float4*)&hsm[r][0];
        float acc = 0.0f;
#pragma unroll
        for (int m = 0; m < 16; m++) {
            float4 a  = wrow[lane + 32 * m];
            float4 h4 = hrow[lane + 32 * m];
            acc += a.x * h4.x + a.y * h4.y + a.z * h4.z + a.w * h4.w;
        }
#pragma unroll
        for (int o = 16; o > 0; o >>= 1) acc += __shfl_xor_sync(0xffffffffu, acc, o);
        if (lane == 0) g_feats[(s0 + r) * TN + tag] = acc + __ldg(&bd[tag]);
    }
}

// ---------------------------------------------------------------------------
// Kernel D: Viterbi forward + chunked smem backtrack (validated).
// 2 threads per tag row, 4 compare chains each; first-max tie-break preserved.
// ---------------------------------------------------------------------------
__global__ void __launch_bounds__(128) viterbi_kernel(
    const float* __restrict__ trans, float* __restrict__ out, int out_size)
{
    __shared__ float fvb[2][TN];
    __shared__ unsigned char bpc[256 * TN];   // 12 KB backtrack chunk
    const int tid  = threadIdx.x;
    const int row  = tid >> 1;
    const int half = tid & 1;

    float tr[24];
    if (tid < 96) {
#pragma unroll
        for (int j = 0; j < 24; j++) tr[j] = __ldg(&trans[row * TN + half * 24 + j]);
    }
    if (tid < TN) fvb[0][tid] = (tid == START_TAG) ? 0.0f : NEGV;
    __syncthreads();

    for (int s = 0; s < SN; s++) {
        const float* fv = fvb[s & 1];
        float* fvn = fvb[(s + 1) & 1];
        if (tid < 96) {
            float feat = half ? 0.0f : __ldg(&g_feats[s * TN + row]);
            const int jb = half * 24;
            float b0 = fv[jb + 0]  + tr[0];  int a0 = jb + 0;
            float b1 = fv[jb + 6]  + tr[6];  int a1 = jb + 6;
            float b2 = fv[jb + 12] + tr[12]; int a2 = jb + 12;
            float b3 = fv[jb + 18] + tr[18]; int a3 = jb + 18;
#pragma unroll
            for (int k = 1; k < 6; k++) {
                float v0 = fv[jb + k]      + tr[k];      if (v0 > b0) { b0 = v0; a0 = jb + k; }
                float v1 = fv[jb + 6 + k]  + tr[6 + k];  if (v1 > b1) { b1 = v1; a1 = jb + 6 + k; }
                float v2 = fv[jb + 12 + k] + tr[12 + k]; if (v2 > b2) { b2 = v2; a2 = jb + 12 + k; }
                float v3 = fv[jb + 18 + k] + tr[18 + k]; if (v3 > b3) { b3 = v3; a3 = jb + 18 + k; }
            }
            if (b1 > b0) { b0 = b1; a0 = a1; }
            if (b3 > b2) { b2 = b3; a2 = a3; }
            if (b2 > b0) { b0 = b2; a0 = a2; }
            float bo = __shfl_xor_sync(0xffffffffu, b0, 1);
            int   ao = __shfl_xor_sync(0xffffffffu, a0, 1);
            if (half == 0) {
                if (bo > b0) { b0 = bo; a0 = ao; }  // other half's indices all larger
                fvn[row] = b0 + feat;
                g_bp[s * TN + row] = (unsigned char)a0;
            }
        }
        __syncthreads();
    }

    __shared__ int s_arg;
    if (tid == 0) {
        float best = -3.4e38f; int arg = 0;
        const float* fvf = fvb[SN & 1];
        for (int i = 0; i < TN; i++) {
            float v = fvf[i] + __ldg(&trans[END_TAG * TN + i]);
            if (v > best) { best = v; arg = i; }
        }
        if (out_size > 0) out[0] = best;
        if (SN < out_size) out[SN] = (float)arg;
        s_arg = arg;
    }
    __syncthreads();

    int cur = s_arg;  // live in tid 0 only
    for (int c0 = SN - 256; c0 >= 0; c0 -= 256) {
        const uint4* src = (const uint4*)&g_bp[c0 * TN];
        uint4* dst = (uint4*)bpc;
        for (int i = tid; i < 256 * TN / 16; i += 128) dst[i] = src[i];
        __syncthreads();
        if (tid == 0) {
            int hi = c0 + 255; if (hi > SN - 1) hi = SN - 1;
            int lo = (c0 > 0) ? c0 : 1;
            for (int s = hi; s >= lo; s--) {
                cur = bpc[(s - c0) * TN + cur];
                if (s < out_size) out[s] = (float)cur;
            }
        }
        __syncthreads();
    }
}

// ---------------------------------------------------------------------------
// Launch
// ---------------------------------------------------------------------------
extern "C" void kernel_launch(void* const* d_in, const int* in_sizes, int n_in,
                              void* d_out, int out_size)
{
    const float* sentence    = (const float*)d_in[0];
    const float* W_ih_f      = (const float*)d_in[1];
    const float* W_hh_f      = (const float*)d_in[2];
    const float* b_ih_f      = (const float*)d_in[3];
    const float* b_hh_f      = (const float*)d_in[4];
    const float* W_ih_b      = (const float*)d_in[5];
    const float* W_hh_b      = (const float*)d_in[6];
    const float* b_ih_b      = (const float*)d_in[7];
    const float* b_hh_b      = (const float*)d_in[8];
    const float* W_dense     = (const float*)d_in[9];
    const float* b_dense     = (const float*)d_in[10];
    const float* transitions = (const float*)d_in[11];
    float* out = (float*)d_out;

    (void)in_sizes; (void)n_in;

    cudaFuncSetAttribute(lstm_kernel, cudaFuncAttributeMaxDynamicSharedMemorySize, LSTM_SMEM);

    init_kernel<<<64, 256>>>();

    dim3 ggemm(4 * HN / BN, SN / BM, 2);
    xi_gemm_kernel<<<ggemm, 256>>>(sentence, W_ih_f, W_ih_b,
                                   b_ih_f, b_hh_f, b_ih_b, b_hh_b);

    lstm_kernel<<<NBLK, 256, LSTM_SMEM>>>(W_hh_f, W_hh_b);

    dense_kernel<<<SN / 4, 256>>>(W_dense, b_dense);

    viterbi_kernel<<<1, 128>>>(transitions, out, out_size);
}